// round 15
// baseline (speedup 1.0000x reference)
#include <cuda_runtime.h>
#include <cuda_fp16.h>
#include <math.h>

#define VOCAB1 50001
#define NEMB   256
#define NSEQ   64
#define NFEAT  512
#define NBATCH 1024
#define NROWS  2048

#define NTILES 392
#define VPAD   (NTILES * 128)

#define A_CH_HALFS 5120
#define A_TILE_HALFS (8 * A_CH_HALFS)

typedef unsigned long long ull;

// ---------------- device scratch ----------------
__device__ float  g_EW[(size_t)VPAD * NFEAT];          // projected embeddings
__device__ __half g_Uv[8 * 65536];                     // U hi/lo, 8 n-slices (resident layout)
__device__ __half g_Ah[(size_t)NTILES * A_TILE_HALFS]; // emb hi, chunked tiles
__device__ __half g_Al[(size_t)NTILES * A_TILE_HALFS]; // emb lo
__device__ __half g_W16[8 * 32768];                    // W hi/lo, 8 n-slices x 8 chunks

// ---------------- common helpers ----------------
__device__ __forceinline__ unsigned smem_u32(const void* p) {
    unsigned a;
    asm("{ .reg .u64 t; cvta.to.shared.u64 t, %1; cvt.u32.u64 %0, t; }" : "=r"(a) : "l"(p));
    return a;
}
__device__ __forceinline__ void mbar_init(unsigned a, unsigned cnt) {
    asm volatile("mbarrier.init.shared.b64 [%0], %1;" :: "r"(a), "r"(cnt) : "memory");
}
__device__ __forceinline__ void mbar_wait(unsigned a, unsigned par) {
    asm volatile(
        "{\n\t.reg .pred P;\n\t"
        "WL_%=:\n\t"
        "mbarrier.try_wait.parity.acquire.cta.shared::cta.b64 P, [%0], %1, 0x989680;\n\t"
        "@!P bra WL_%=;\n\t}"
        :: "r"(a), "r"(par) : "memory");
}
__device__ __forceinline__ void mbar_expect(unsigned a, unsigned bytes) {
    asm volatile("mbarrier.arrive.expect_tx.shared.b64 _, [%0], %1;"
                 :: "r"(a), "r"(bytes) : "memory");
}
__device__ __forceinline__ void raw_bulk(unsigned dst, const void* src,
                                         unsigned bytes, unsigned mbar) {
    asm volatile(
        "cp.async.bulk.shared::cta.global.mbarrier::complete_tx::bytes [%0], [%1], %2, [%3];"
        :: "r"(dst), "l"(src), "r"(bytes), "r"(mbar) : "memory");
}
__device__ __forceinline__ void bulk_load(unsigned dst, const void* src,
                                          unsigned bytes, unsigned mbar) {
    mbar_expect(mbar, bytes);
    raw_bulk(dst, src, bytes, mbar);
}

// ---------------- cluster helpers ----------------
__device__ __forceinline__ unsigned cl_rank() {
    unsigned r; asm("mov.u32 %0, %%cluster_ctarank;" : "=r"(r)); return r;
}
__device__ __forceinline__ unsigned mapa_u32(unsigned local, unsigned rank) {
    unsigned r;
    asm("mapa.shared::cluster.u32 %0, %1, %2;" : "=r"(r) : "r"(local), "r"(rank));
    return r;
}
__device__ __forceinline__ unsigned ldc32(unsigned a) {
    unsigned v; asm("ld.shared::cluster.b32 %0, [%1];" : "=r"(v) : "r"(a)); return v;
}
__device__ __forceinline__ void cluster_sync() {
    asm volatile("barrier.cluster.arrive.aligned;" ::: "memory");
    asm volatile("barrier.cluster.wait.aligned;" ::: "memory");
}

// ---------------- mma.sync / ldmatrix -------------------------------------
__device__ __forceinline__ void ldsm_x4(unsigned &r0, unsigned &r1,
                                        unsigned &r2, unsigned &r3, unsigned addr) {
    asm volatile("ldmatrix.sync.aligned.m8n8.x4.shared.b16 {%0,%1,%2,%3}, [%4];"
                 : "=r"(r0), "=r"(r1), "=r"(r2), "=r"(r3) : "r"(addr));
}
__device__ __forceinline__ void mma16816(float* c,
                                         unsigned a0, unsigned a1, unsigned a2, unsigned a3,
                                         unsigned b0, unsigned b1) {
    asm volatile("mma.sync.aligned.m16n8k16.row.col.f32.f16.f16.f32 "
                 "{%0,%1,%2,%3}, {%4,%5,%6,%7}, {%8,%9}, {%0,%1,%2,%3};"
                 : "+f"(c[0]), "+f"(c[1]), "+f"(c[2]), "+f"(c[3])
                 : "r"(a0), "r"(a1), "r"(a2), "r"(a3), "r"(b0), "r"(b1));
}

// W/U slice swizzle (nl in [0,64))
__device__ __forceinline__ int w_hidx(int nl, int kk) {
    return nl * 32 + (((((kk >> 3) + (nl >> 1)) & 3)) << 3) + (kk & 7);
}
// h publish swizzle: [128 rows][64 feats], byte offset within 16KB block
__device__ __forceinline__ int h_swz(int r, int f) {
    return r * 128 + ((((f >> 3) + r) & 7) << 4) + (f & 7) * 2;
}

// ---------------- prep: U -> resident n-sliced layout ---------------------
__global__ __launch_bounds__(256) void prepU_kernel(const float* __restrict__ U)
{
    int idx = blockIdx.x * 256 + threadIdx.x;
    if (idx < NFEAT * NFEAT) {
        int k = idx >> 9, n = idx & 511;
        float v = U[idx];
        __half hi = __float2half_rn(v);
        __half lo = __float2half_rn(v - __half2float(hi));
        int j = n >> 6, nl = n & 63;
        int c = k >> 5, kk = k & 31;
        int h = c * 2048 + w_hidx(nl, kk);
        g_Uv[j * 65536 + h]         = hi;
        g_Uv[j * 65536 + 32768 + h] = lo;
    }
}

// ---------------- prep: emb -> fp16 hi/lo k-chunked tiles -----------------
__global__ __launch_bounds__(256) void prepA_kernel(const float* __restrict__ emb)
{
    const int t = blockIdx.x;
    const size_t base = (size_t)t * A_TILE_HALFS;
    for (int idx = threadIdx.x; idx < 128 * (NEMB / 2); idx += 256) {
        int r = idx >> 7, kp = idx & 127;
        int k = kp * 2;
        int grow = t * 128 + r;
        float2 v = (grow < VOCAB1)
                   ? *(const float2*)(emb + (size_t)grow * NEMB + k)
                   : make_float2(0.f, 0.f);
        __half h0 = __float2half_rn(v.x);
        __half h1 = __float2half_rn(v.y);
        __half l0 = __float2half_rn(v.x - __half2float(h0));
        __half l1 = __float2half_rn(v.y - __half2float(h1));
        int c = k >> 5, kk = k & 31;
        size_t off = base + (size_t)c * A_CH_HALFS + r * 40 + kk;
        *(__half2*)(g_Ah + off) = __halves2half2(h0, h1);
        *(__half2*)(g_Al + off) = __halves2half2(l0, l1);
    }
}

// ---------------- prep: W -> fp16 hi/lo sliced/swizzled -------------------
__global__ __launch_bounds__(256) void prepW_kernel(const float* __restrict__ W)
{
    int idx = blockIdx.x * 256 + threadIdx.x;
    if (idx < NEMB * NFEAT) {
        int k = idx >> 9, n = idx & 511;
        float v = W[idx];
        __half hi = __float2half_rn(v);
        __half lo = __float2half_rn(v - __half2float(hi));
        int j = n >> 6, nl = n & 63;
        int c = k >> 5, kk = k & 31;
        int h = c * 2048 + w_hidx(nl, kk);
        g_W16[j * 32768 + h]         = hi;
        g_W16[j * 32768 + 16384 + h] = lo;
    }
}

// ---------------- Kernel 1: EW = emb @ W, pipelined mma (R13) -------------
#define EWC_AH 0
#define EWC_AL 10240
#define EWC_B  20480
#define EWC_BYTES 36864
#define EW_BUF0  1024
#define EW_TOTAL (EW_BUF0 + 2 * EWC_BYTES)

__global__ __launch_bounds__(256) void ew_mma_kernel()
{
    extern __shared__ __align__(1024) char esm[];
    const unsigned smb = smem_u32(esm);
    const int tid  = threadIdx.x;
    const int wid  = tid >> 5;
    const int lane = tid & 31;
    const int sp   = blockIdx.x;
    const int tile = blockIdx.y;
    const unsigned mb0 = smb, mb1 = smb + 8;
    const unsigned buf0 = smb + EW_BUF0;
    const unsigned buf1 = buf0 + EWC_BYTES;

    const __half* Ah = g_Ah + (size_t)tile * A_TILE_HALFS;
    const __half* Al = g_Al + (size_t)tile * A_TILE_HALFS;
    const __half* W0 = g_W16 + (size_t)(2 * sp) * 32768;
    const __half* W1 = W0 + 32768;

    if (tid == 0) { mbar_init(mb0, 1); mbar_init(mb1, 1); }
    __syncthreads();
    if (tid == 0) {
#pragma unroll
        for (int s = 0; s < 2; s++) {
            const unsigned mb = s ? mb1 : mb0;
            const unsigned bf = s ? buf1 : buf0;
            mbar_expect(mb, EWC_BYTES);
            raw_bulk(bf + EWC_AH, Ah + s * A_CH_HALFS, 10240, mb);
            raw_bulk(bf + EWC_AL, Al + s * A_CH_HALFS, 10240, mb);
            raw_bulk(bf + EWC_B,          W0 + s * 2048,         4096, mb);
            raw_bulk(bf + EWC_B + 4096,   W0 + 16384 + s * 2048, 4096, mb);
            raw_bulk(bf + EWC_B + 8192,   W1 + s * 2048,         4096, mb);
            raw_bulk(bf + EWC_B + 12288,  W1 + 16384 + s * 2048, 4096, mb);
        }
    }

    const int a_row  = lane & 15;
    const int a_koct = (lane >> 4) * 8;
    const int b_i    = lane & 7;
    const int b_seg  = lane >> 3;
    const int b_nadd = (b_seg & 2) ? 8 : 0;
    const int b_kadd = (b_seg & 1) ? 8 : 0;

    float c[2][8][4];
#pragma unroll
    for (int sl = 0; sl < 2; sl++)
#pragma unroll
        for (int nt = 0; nt < 8; nt++)
#pragma unroll
            for (int q = 0; q < 4; q++) c[sl][nt][q] = 0.f;

    unsigned ph0 = 0, ph1 = 0;
#pragma unroll 1
    for (int s = 0; s < 8; s++) {
        const int bsel = s & 1;
        if (bsel) { mbar_wait(mb1, ph1); ph1 ^= 1; }
        else      { mbar_wait(mb0, ph0); ph0 ^= 1; }
        const unsigned ub = bsel ? buf1 : buf0;
#pragma unroll
        for (int kt = 0; kt < 2; kt++) {
            const int kglob = kt * 16 + a_koct;
            const unsigned aoff = (unsigned)(((wid * 16 + a_row) * 40 + kglob) * 2);
            unsigned ah[4], al[4];
            ldsm_x4(ah[0], ah[1], ah[2], ah[3], ub + EWC_AH + aoff);
            ldsm_x4(al[0], al[1], al[2], al[3], ub + EWC_AL + aoff);
            const int kk = kt * 16 + b_kadd;
#pragma unroll
            for (int sl = 0; sl < 2; sl++) {
                const unsigned bbase = ub + EWC_B + sl * 8192;
#pragma unroll
                for (int p = 0; p < 4; p++) {
                    const int nl = p * 16 + b_nadd + b_i;
                    const unsigned boff = (unsigned)(w_hidx(nl, kk) * 2);
                    unsigned bh0, bh1, bh2, bh3, bl0, bl1, bl2, bl3;
                    ldsm_x4(bh0, bh1, bh2, bh3, bbase + boff);
                    ldsm_x4(bl0, bl1, bl2, bl3, bbase + 4096 + boff);
                    float* cp0 = c[sl][2 * p];
                    float* cp1 = c[sl][2 * p + 1];
                    mma16816(cp0, ah[0], ah[1], ah[2], ah[3], bh0, bh1);
                    mma16816(cp1, ah[0], ah[1], ah[2], ah[3], bh2, bh3);
                    mma16816(cp0, al[0], al[1], al[2], al[3], bh0, bh1);
                    mma16816(cp1, al[0], al[1], al[2], al[3], bh2, bh3);
                    mma16816(cp0, ah[0], ah[1], ah[2], ah[3], bl0, bl1);
                    mma16816(cp1, ah[0], ah[1], ah[2], ah[3], bl2, bl3);
                }
            }
        }
        __syncthreads();
        if (tid == 0 && s + 2 < 8) {
            const int sn = s + 2;
            const unsigned mb = bsel ? mb1 : mb0;
            const unsigned bf = bsel ? buf1 : buf0;
            mbar_expect(mb, EWC_BYTES);
            raw_bulk(bf + EWC_AH, Ah + sn * A_CH_HALFS, 10240, mb);
            raw_bulk(bf + EWC_AL, Al + sn * A_CH_HALFS, 10240, mb);
            raw_bulk(bf + EWC_B,          W0 + sn * 2048,         4096, mb);
            raw_bulk(bf + EWC_B + 4096,   W0 + 16384 + sn * 2048, 4096, mb);
            raw_bulk(bf + EWC_B + 8192,   W1 + sn * 2048,         4096, mb);
            raw_bulk(bf + EWC_B + 12288,  W1 + 16384 + sn * 2048, 4096, mb);
        }
    }

    const int grow = tile * 128 + wid * 16;
    const int r1 = lane >> 2;
    const int r2 = r1 + 8;
#pragma unroll
    for (int sl = 0; sl < 2; sl++) {
        const int colbase = (2 * sp + sl) * 64;
#pragma unroll
        for (int nt = 0; nt < 8; nt++) {
            const int col = colbase + nt * 8 + (lane & 3) * 2;
            *(float2*)(g_EW + (size_t)(grow + r1) * NFEAT + col) =
                make_float2(c[sl][nt][0], c[sl][nt][1]);
            *(float2*)(g_EW + (size_t)(grow + r2) * NFEAT + col) =
                make_float2(c[sl][nt][2], c[sl][nt][3]);
        }
    }
}

// ---------------- Kernel 2: cluster-resident-U recurrent scan -------------
// 16 clusters x 8 CTAs. Cluster handles 128 rows; CTA rank j owns U n-slice
// [512k x 64n] hi/lo resident in SMEM (128KB, loaded once) and computes
// h_new[:, slice] for all 128 rows. A-operand (h) fragments read from peers'
// publish buffers via ld.shared::cluster. Double-buffered publish, one
// cluster barrier per step. U L2 traffic: 8.4GB -> 16MB.
#define RC_SID   16                   // 128 ints at bytes [16, 528)
#define RC_U     1024                 // hi 64KB, lo 64KB
#define RC_PB    (RC_U + 131072)      // 2 x (hi 16KB + lo 16KB)
#define RC_TOTAL (RC_PB + 2 * 32768)  // 197632 bytes

__global__ __launch_bounds__(256, 1) __cluster_dims__(8, 1, 1)
void rnn_cluster_kernel(
    const int*  __restrict__ ids1,
    const int*  __restrict__ ids2,
    const float* __restrict__ bias,
    float* __restrict__ out)
{
    extern __shared__ __align__(1024) char rsm[];
    const unsigned smb = smem_u32(rsm);
    const int tid  = threadIdx.x;
    const int wid  = tid >> 5;
    const int lane = tid & 31;
    const unsigned rank = cl_rank();
    const int cid  = blockIdx.x >> 3;           // cluster id
    const int rb0  = cid * 128;                 // global row base (cluster)
    const int nbase = (int)rank * 64;           // feature slice base
    const int* myids = (rb0 < NBATCH) ? ids1 : ids2;
    const int rbase  = rb0 & (NBATCH - 1);

    int* s_id = (int*)(rsm + RC_SID);
    const unsigned mbU = smb;                   // bytes [0,8)
    const unsigned ub  = smb + RC_U;

    // zero publish buffer 0 (hi+lo, 32KB)
    for (int i = tid; i < 8192; i += 256)
        *(unsigned*)(rsm + RC_PB + i * 4) = 0u;
    if (tid == 0) {
        mbar_init(mbU, 1);
        bulk_load(ub, g_Uv + (size_t)rank * 65536, 131072, mbU);
    }
    __syncthreads();
    cluster_sync();            // all PB0 zeroed cluster-wide
    mbar_wait(mbU, 0);         // own U slice resident

    // bias for this thread's columns
    float2 bias2[8];
#pragma unroll
    for (int nt = 0; nt < 8; nt++)
        bias2[nt] = *(const float2*)(bias + nbase + nt * 8 + (lane & 3) * 2);

    const int b_i    = lane & 7;
    const int b_seg  = lane >> 3;
    const int b_nadd = (b_seg & 2) ? 8 : 0;
    const int b_kadd = (b_seg & 1) ? 8 : 0;
    const int frow   = wid * 16 + (lane >> 2);  // fragment row (cluster-local)
    const int fcol0  = (lane & 3) * 2;          // fragment col base

    for (int t = 0; t < NSEQ; t++) {
        if (tid < 128) s_id[tid] = myids[(rbase + tid) * NSEQ + t];
        __syncthreads();

        const unsigned pb_cur = smb + RC_PB + (unsigned)((t & 1) * 32768);
        const unsigned pb_nxt = smb + RC_PB + (unsigned)(((t + 1) & 1) * 32768);

        float c[8][4];
#pragma unroll
        for (int nt = 0; nt < 8; nt++)
#pragma unroll
            for (int q = 0; q < 4; q++) c[nt][q] = 0.f;

#pragma unroll 1
        for (int s = 0; s < 8; s++) {
            const int p = ((int)rank + s) & 7;          // staggered peer order
            const unsigned rbase_hi = mapa_u32(pb_cur, (unsigned)p);
            const unsigned rbase_lo = rbase_hi + 16384;
#pragma unroll
            for (int kt = 0; kt < 4; kt++) {
                // A fragments from peer p's h slice (f = k-local within 64)
                const int f0 = kt * 16 + fcol0;
                const int f1 = f0 + 8;
                const unsigned o00 = (unsigned)h_swz(frow,     f0);
                const unsigned o10 = (unsigned)h_swz(frow + 8, f0);
                const unsigned o01 = (unsigned)h_swz(frow,     f1);
                const unsigned o11 = (unsigned)h_swz(frow + 8, f1);
                unsigned ah0 = ldc32(rbase_hi + o00);
                unsigned ah1 = ldc32(rbase_hi + o10);
                unsigned ah2 = ldc32(rbase_hi + o01);
                unsigned ah3 = ldc32(rbase_hi + o11);
                unsigned al0 = ldc32(rbase_lo + o00);
                unsigned al1 = ldc32(rbase_lo + o10);
                unsigned al2 = ldc32(rbase_lo + o01);
                unsigned al3 = ldc32(rbase_lo + o11);
                // B from resident U slice: k-global = p*64 + kt*16
                const int ch = 2 * p + (kt >> 1);
                const int kk = (kt & 1) * 16 + b_kadd;
#pragma unroll
                for (int pn = 0; pn < 4; pn++) {
                    const int nl = pn * 16 + b_nadd + b_i;
                    const unsigned boff = (unsigned)((ch * 2048 + w_hidx(nl, kk)) * 2);
                    unsigned bh0, bh1, bh2, bh3, bl0, bl1, bl2, bl3;
                    ldsm_x4(bh0, bh1, bh2, bh3, ub + boff);
                    ldsm_x4(bl0, bl1, bl2, bl3, ub + 65536 + boff);
                    mma16816(c[2 * pn],     ah0, ah1, ah2, ah3, bh0, bh1);
                    mma16816(c[2 * pn + 1], ah0, ah1, ah2, ah3, bh2, bh3);
                    mma16816(c[2 * pn],     al0, al1, al2, al3, bh0, bh1);
                    mma16816(c[2 * pn + 1], al0, al1, al2, al3, bh2, bh3);
                    mma16816(c[2 * pn],     ah0, ah1, ah2, ah3, bl0, bl1);
                    mma16816(c[2 * pn + 1], ah0, ah1, ah2, ah3, bl2, bl3);
                }
            }
        }

        // epilogue: x gather + bias + tanh + masked update -> publish nxt
        {
            const int r1g = frow;          // cluster-local rows
            const int r2g = frow + 8;
            const int gid1 = s_id[r1g], gid2 = s_id[r2g];
            const float* e1 = g_EW + (size_t)gid1 * NFEAT + nbase;
            const float* e2 = g_EW + (size_t)gid2 * NFEAT + nbase;
            const bool m1 = (gid1 != 0), m2 = (gid2 != 0);
#pragma unroll
            for (int nt = 0; nt < 8; nt++) {
                const int col = nt * 8 + fcol0;
                const unsigned sw1 = (unsigned)h_swz(r1g, col);
                const unsigned sw2 = (unsigned)h_swz(r2g, col);
                if (m1) {
                    float2 X = *(const float2*)(e1 + col);
                    float v0 = tanhf(c[nt][0] + X.x + bias2[nt].x);
                    float v1 = tanhf(c[nt][1] + X.y + bias2[nt].y);
                    __half p0 = __float2half_rn(v0);
                    __half p1 = __float2half_rn(v1);
                    *(__half2*)(rsm + (pb_nxt - smb) + sw1) = __halves2half2(p0, p1);
                    *(__half2*)(rsm + (pb_nxt - smb) + 16384 + sw1) =
                        __halves2half2(__float2half_rn(v0 - __half2float(p0)),
                                       __float2half_rn(v1 - __half2float(p1)));
                } else {
                    *(__half2*)(rsm + (pb_nxt - smb) + sw1) =
                        *(__half2*)(rsm + (pb_cur - smb) + sw1);
                    *(__half2*)(rsm + (pb_nxt - smb) + 16384 + sw1) =
                        *(__half2*)(rsm + (pb_cur - smb) + 16384 + sw1);
                }
                if (m2) {
                    float2 X = *(const float2*)(e2 + col);
                    float v2 = tanhf(c[nt][2] + X.x + bias2[nt].x);
                    float v3 = tanhf(c[nt][3] + X.y + bias2[nt].y);
                    __half p2 = __float2half_rn(v2);
                    __half p3 = __float2half_rn(v3);
                    *(__half2*)(rsm + (pb_nxt - smb) + sw2) = __halves2half2(p2, p3);
                    *(__half2*)(rsm + (pb_nxt - smb) + 16384 + sw2) =
                        __halves2half2(__float2half_rn(v2 - __half2float(p2)),
                                       __float2half_rn(v3 - __half2float(p3)));
                } else {
                    *(__half2*)(rsm + (pb_nxt - smb) + sw2) =
                        *(__half2*)(rsm + (pb_cur - smb) + sw2);
                    *(__half2*)(rsm + (pb_nxt - smb) + 16384 + sw2) =
                        *(__half2*)(rsm + (pb_cur - smb) + 16384 + sw2);
                }
            }
        }
        cluster_sync();   // publishes visible cluster-wide before next step
    }

    // final h in PB[(NSEQ)&1] = PB0 : write out this CTA's slice
    const unsigned pbf = (unsigned)(RC_PB + ((NSEQ & 1) * 32768));
    for (int i = tid; i < 128 * 64; i += 256) {
        const int r = i >> 6, f = i & 63;
        const unsigned sw = (unsigned)h_swz(r, f);
        float hv = __half2float(*(__half*)(rsm + pbf + sw)) +
                   __half2float(*(__half*)(rsm + pbf + 16384 + sw));
        out[(size_t)(rb0 + r) * NFEAT + nbase + f] = hv;
    }
    cluster_sync();   // no CTA exits while peers may still read its SMEM
}

// ---------------- Kernel 3: cosine similarity -----------------------------
__global__ __launch_bounds__(256) void sim_kernel(float* __restrict__ out)
{
    const int b    = blockIdx.x * 8 + (threadIdx.x >> 5);
    const int lane = threadIdx.x & 31;
    const float* s1 = out + (size_t)b * NFEAT;
    const float* s2 = out + (size_t)(NBATCH + b) * NFEAT;
    float dot = 0.f, q1 = 0.f, q2 = 0.f;
    for (int j = lane; j < NFEAT; j += 32) {
        float a = s1[j], c = s2[j];
        dot += a * c;
        q1  += a * a;
        q2  += c * c;
    }
#pragma unroll
    for (int o = 16; o > 0; o >>= 1) {
        dot += __shfl_xor_sync(0xffffffffu, dot, o);
        q1  += __shfl_xor_sync(0xffffffffu, q1,  o);
        q2  += __shfl_xor_sync(0xffffffffu, q2,  o);
    }
    if (lane == 0) {
        float n1 = sqrtf(fmaxf(q1, 1e-12f));
        float n2 = sqrtf(fmaxf(q2, 1e-12f));
        out[(size_t)NROWS * NFEAT + b] = dot / (n1 * n2);
    }
}

// ---------------- launch -------------------------------------------------
extern "C" void kernel_launch(void* const* d_in, const int* in_sizes, int n_in,
                              void* d_out, int out_size)
{
    (void)in_sizes; (void)n_in; (void)out_size;
    const int*   ids1 = (const int*)  d_in[0];
    const int*   ids2 = (const int*)  d_in[1];
    const float* emb  = (const float*)d_in[2];
    const float* W    = (const float*)d_in[3];
    const float* U    = (const float*)d_in[4];
    const float* bias = (const float*)d_in[5];
    float* out = (float*)d_out;

    cudaFuncSetAttribute(ew_mma_kernel,
                         cudaFuncAttributeMaxDynamicSharedMemorySize, EW_TOTAL);
    cudaFuncSetAttribute(rnn_cluster_kernel,
                         cudaFuncAttributeMaxDynamicSharedMemorySize, RC_TOTAL);

    prepU_kernel<<<(NFEAT * NFEAT + 255) / 256, 256>>>(U);
    prepA_kernel<<<NTILES, 256>>>(emb);
    prepW_kernel<<<(NEMB * NFEAT + 255) / 256, 256>>>(W);
    dim3 gew(4, NTILES);
    ew_mma_kernel<<<gew, 256, EW_TOTAL>>>();
    rnn_cluster_kernel<<<128, 256, RC_TOTAL>>>(ids1, ids2, bias, out);
    sim_kernel<<<NBATCH / 8, 256>>>(out);
}

// round 16
// speedup vs baseline: 4.8893x; 4.8893x over previous
#include <cuda_runtime.h>
#include <cuda_fp16.h>
#include <math.h>

#define VOCAB1 50001
#define NEMB   256
#define NSEQ   64
#define NFEAT  512
#define NBATCH 1024
#define NROWS  2048

#define NTILES 392
#define VPAD   (NTILES * 128)

#define A_CH_HALFS 5120
#define A_TILE_HALFS (8 * A_CH_HALFS)

typedef unsigned long long ull;

// ---------------- device scratch ----------------
__device__ float  g_EW[(size_t)VPAD * NFEAT];
__device__ __half g_U16[16 * 32768];                   // U hi/lo, 16 k-chunks, swizzled
__device__ __half g_Ah[(size_t)NTILES * A_TILE_HALFS];
__device__ __half g_Al[(size_t)NTILES * A_TILE_HALFS];
__device__ __half g_W16[8 * 32768];

// ---------------- common helpers ----------------
__device__ __forceinline__ unsigned smem_u32(const void* p) {
    unsigned a;
    asm("{ .reg .u64 t; cvta.to.shared.u64 t, %1; cvt.u32.u64 %0, t; }" : "=r"(a) : "l"(p));
    return a;
}
__device__ __forceinline__ void mbar_init(unsigned a, unsigned cnt) {
    asm volatile("mbarrier.init.shared.b64 [%0], %1;" :: "r"(a), "r"(cnt) : "memory");
}
__device__ __forceinline__ void mbar_wait(unsigned a, unsigned par) {
    asm volatile(
        "{\n\t.reg .pred P;\n\t"
        "WL_%=:\n\t"
        "mbarrier.try_wait.parity.acquire.cta.shared::cta.b64 P, [%0], %1, 0x989680;\n\t"
        "@!P bra WL_%=;\n\t}"
        :: "r"(a), "r"(par) : "memory");
}
__device__ __forceinline__ void mbar_expect(unsigned a, unsigned bytes) {
    asm volatile("mbarrier.arrive.expect_tx.shared.b64 _, [%0], %1;"
                 :: "r"(a), "r"(bytes) : "memory");
}
__device__ __forceinline__ void raw_bulk(unsigned dst, const void* src,
                                         unsigned bytes, unsigned mbar) {
    asm volatile(
        "cp.async.bulk.shared::cta.global.mbarrier::complete_tx::bytes [%0], [%1], %2, [%3];"
        :: "r"(dst), "l"(src), "r"(bytes), "r"(mbar) : "memory");
}
__device__ __forceinline__ void bulk_load(unsigned dst, const void* src,
                                          unsigned bytes, unsigned mbar) {
    mbar_expect(mbar, bytes);
    raw_bulk(dst, src, bytes, mbar);
}

// ---------------- mma.sync / ldmatrix -------------------------------------
__device__ __forceinline__ void ldsm_x4(unsigned &r0, unsigned &r1,
                                        unsigned &r2, unsigned &r3, unsigned addr) {
    asm volatile("ldmatrix.sync.aligned.m8n8.x4.shared.b16 {%0,%1,%2,%3}, [%4];"
                 : "=r"(r0), "=r"(r1), "=r"(r2), "=r"(r3) : "r"(addr));
}
__device__ __forceinline__ void mma16816(float* c,
                                         unsigned a0, unsigned a1, unsigned a2, unsigned a3,
                                         unsigned b0, unsigned b1) {
    asm volatile("mma.sync.aligned.m16n8k16.row.col.f32.f16.f16.f32 "
                 "{%0,%1,%2,%3}, {%4,%5,%6,%7}, {%8,%9}, {%0,%1,%2,%3};"
                 : "+f"(c[0]), "+f"(c[1]), "+f"(c[2]), "+f"(c[3])
                 : "r"(a0), "r"(a1), "r"(a2), "r"(a3), "r"(b0), "r"(b1));
}
// fp16-accumulate variant (2x rate on most parts); D = {c0c1, c2c3} packed halves
__device__ __forceinline__ void mma16816_h(unsigned &d0, unsigned &d1,
                                           unsigned a0, unsigned a1, unsigned a2, unsigned a3,
                                           unsigned b0, unsigned b1) {
    asm volatile("mma.sync.aligned.m16n8k16.row.col.f16.f16.f16.f16 "
                 "{%0,%1}, {%2,%3,%4,%5}, {%6,%7}, {%0,%1};"
                 : "+r"(d0), "+r"(d1)
                 : "r"(a0), "r"(a1), "r"(a2), "r"(a3), "r"(b0), "r"(b1));
}

// U chunk swizzle (n=512 rows of 32 kk)
__device__ __forceinline__ int u_hidx(int n, int kk) {
    return n * 32 + (((((kk >> 3) + (n >> 1)) & 3)) << 3) + (kk & 7);
}
// W slice swizzle (nl in [0,64))
__device__ __forceinline__ int w_hidx(int nl, int kk) {
    return nl * 32 + (((((kk >> 3) + (nl >> 1)) & 3)) << 3) + (kk & 7);
}

// ---------------- prep: U -> fp16 hi/lo swizzled chunks -------------------
__global__ __launch_bounds__(256) void prepU_kernel(const float* __restrict__ U)
{
    int idx = blockIdx.x * 256 + threadIdx.x;
    if (idx < NFEAT * NFEAT) {
        int k = idx >> 9, n = idx & 511;
        float v = U[idx];
        __half hi = __float2half_rn(v);
        __half lo = __float2half_rn(v - __half2float(hi));
        int c = k >> 5, kk = k & 31;
        int h = u_hidx(n, kk);
        g_U16[c * 32768 + h]         = hi;
        g_U16[c * 32768 + 16384 + h] = lo;
    }
}

// ---------------- prep: emb -> fp16 hi/lo k-chunked tiles (half2) ---------
__global__ __launch_bounds__(256) void prepA_kernel(const float* __restrict__ emb)
{
    const int t = blockIdx.x;
    const size_t base = (size_t)t * A_TILE_HALFS;
    for (int idx = threadIdx.x; idx < 128 * (NEMB / 2); idx += 256) {
        int r = idx >> 7, kp = idx & 127;
        int k = kp * 2;
        int grow = t * 128 + r;
        float2 v = (grow < VOCAB1)
                   ? *(const float2*)(emb + (size_t)grow * NEMB + k)
                   : make_float2(0.f, 0.f);
        __half h0 = __float2half_rn(v.x);
        __half h1 = __float2half_rn(v.y);
        __half l0 = __float2half_rn(v.x - __half2float(h0));
        __half l1 = __float2half_rn(v.y - __half2float(h1));
        int c = k >> 5, kk = k & 31;
        size_t off = base + (size_t)c * A_CH_HALFS + r * 40 + kk;
        *(__half2*)(g_Ah + off) = __halves2half2(h0, h1);
        *(__half2*)(g_Al + off) = __halves2half2(l0, l1);
    }
}

// ---------------- prep: W -> fp16 hi/lo sliced/swizzled -------------------
__global__ __launch_bounds__(256) void prepW_kernel(const float* __restrict__ W)
{
    int idx = blockIdx.x * 256 + threadIdx.x;
    if (idx < NEMB * NFEAT) {
        int k = idx >> 9, n = idx & 511;
        float v = W[idx];
        __half hi = __float2half_rn(v);
        __half lo = __float2half_rn(v - __half2float(hi));
        int j = n >> 6, nl = n & 63;
        int c = k >> 5, kk = k & 31;
        int h = c * 2048 + w_hidx(nl, kk);
        g_W16[j * 32768 + h]         = hi;
        g_W16[j * 32768 + 16384 + h] = lo;
    }
}

// ---------------- Kernel 1: EW = emb @ W, pipelined mma (R13 proven) ------
#define EWC_AH 0
#define EWC_AL 10240
#define EWC_B  20480
#define EWC_BYTES 36864
#define EW_BUF0  1024
#define EW_TOTAL (EW_BUF0 + 2 * EWC_BYTES)

__global__ __launch_bounds__(256) void ew_mma_kernel()
{
    extern __shared__ __align__(1024) char esm[];
    const unsigned smb = smem_u32(esm);
    const int tid  = threadIdx.x;
    const int wid  = tid >> 5;
    const int lane = tid & 31;
    const int sp   = blockIdx.x;
    const int tile = blockIdx.y;
    const unsigned mb0 = smb, mb1 = smb + 8;
    const unsigned buf0 = smb + EW_BUF0;
    const unsigned buf1 = buf0 + EWC_BYTES;

    const __half* Ah = g_Ah + (size_t)tile * A_TILE_HALFS;
    const __half* Al = g_Al + (size_t)tile * A_TILE_HALFS;
    const __half* W0 = g_W16 + (size_t)(2 * sp) * 32768;
    const __half* W1 = W0 + 32768;

    if (tid == 0) { mbar_init(mb0, 1); mbar_init(mb1, 1); }
    __syncthreads();
    if (tid == 0) {
#pragma unroll
        for (int s = 0; s < 2; s++) {
            const unsigned mb = s ? mb1 : mb0;
            const unsigned bf = s ? buf1 : buf0;
            mbar_expect(mb, EWC_BYTES);
            raw_bulk(bf + EWC_AH, Ah + s * A_CH_HALFS, 10240, mb);
            raw_bulk(bf + EWC_AL, Al + s * A_CH_HALFS, 10240, mb);
            raw_bulk(bf + EWC_B,          W0 + s * 2048,         4096, mb);
            raw_bulk(bf + EWC_B + 4096,   W0 + 16384 + s * 2048, 4096, mb);
            raw_bulk(bf + EWC_B + 8192,   W1 + s * 2048,         4096, mb);
            raw_bulk(bf + EWC_B + 12288,  W1 + 16384 + s * 2048, 4096, mb);
        }
    }

    const int a_row  = lane & 15;
    const int a_koct = (lane >> 4) * 8;
    const int b_i    = lane & 7;
    const int b_seg  = lane >> 3;
    const int b_nadd = (b_seg & 2) ? 8 : 0;
    const int b_kadd = (b_seg & 1) ? 8 : 0;

    float c[2][8][4];
#pragma unroll
    for (int sl = 0; sl < 2; sl++)
#pragma unroll
        for (int nt = 0; nt < 8; nt++)
#pragma unroll
            for (int q = 0; q < 4; q++) c[sl][nt][q] = 0.f;

    unsigned ph0 = 0, ph1 = 0;
#pragma unroll 1
    for (int s = 0; s < 8; s++) {
        const int bsel = s & 1;
        if (bsel) { mbar_wait(mb1, ph1); ph1 ^= 1; }
        else      { mbar_wait(mb0, ph0); ph0 ^= 1; }
        const unsigned ub = bsel ? buf1 : buf0;
#pragma unroll
        for (int kt = 0; kt < 2; kt++) {
            const int kglob = kt * 16 + a_koct;
            const unsigned aoff = (unsigned)(((wid * 16 + a_row) * 40 + kglob) * 2);
            unsigned ah[4], al[4];
            ldsm_x4(ah[0], ah[1], ah[2], ah[3], ub + EWC_AH + aoff);
            ldsm_x4(al[0], al[1], al[2], al[3], ub + EWC_AL + aoff);
            const int kk = kt * 16 + b_kadd;
#pragma unroll
            for (int sl = 0; sl < 2; sl++) {
                const unsigned bbase = ub + EWC_B + sl * 8192;
#pragma unroll
                for (int p = 0; p < 4; p++) {
                    const int nl = p * 16 + b_nadd + b_i;
                    const unsigned boff = (unsigned)(w_hidx(nl, kk) * 2);
                    unsigned bh0, bh1, bh2, bh3, bl0, bl1, bl2, bl3;
                    ldsm_x4(bh0, bh1, bh2, bh3, bbase + boff);
                    ldsm_x4(bl0, bl1, bl2, bl3, bbase + 4096 + boff);
                    float* cp0 = c[sl][2 * p];
                    float* cp1 = c[sl][2 * p + 1];
                    mma16816(cp0, ah[0], ah[1], ah[2], ah[3], bh0, bh1);
                    mma16816(cp1, ah[0], ah[1], ah[2], ah[3], bh2, bh3);
                    mma16816(cp0, al[0], al[1], al[2], al[3], bh0, bh1);
                    mma16816(cp1, al[0], al[1], al[2], al[3], bh2, bh3);
                    mma16816(cp0, ah[0], ah[1], ah[2], ah[3], bl0, bl1);
                    mma16816(cp1, ah[0], ah[1], ah[2], ah[3], bl2, bl3);
                }
            }
        }
        __syncthreads();
        if (tid == 0 && s + 2 < 8) {
            const int sn = s + 2;
            const unsigned mb = bsel ? mb1 : mb0;
            const unsigned bf = bsel ? buf1 : buf0;
            mbar_expect(mb, EWC_BYTES);
            raw_bulk(bf + EWC_AH, Ah + sn * A_CH_HALFS, 10240, mb);
            raw_bulk(bf + EWC_AL, Al + sn * A_CH_HALFS, 10240, mb);
            raw_bulk(bf + EWC_B,          W0 + sn * 2048,         4096, mb);
            raw_bulk(bf + EWC_B + 4096,   W0 + 16384 + sn * 2048, 4096, mb);
            raw_bulk(bf + EWC_B + 8192,   W1 + sn * 2048,         4096, mb);
            raw_bulk(bf + EWC_B + 12288,  W1 + 16384 + sn * 2048, 4096, mb);
        }
    }

    const int grow = tile * 128 + wid * 16;
    const int r1 = lane >> 2;
    const int r2 = r1 + 8;
#pragma unroll
    for (int sl = 0; sl < 2; sl++) {
        const int colbase = (2 * sp + sl) * 64;
#pragma unroll
        for (int nt = 0; nt < 8; nt++) {
            const int col = colbase + nt * 8 + (lane & 3) * 2;
            *(float2*)(g_EW + (size_t)(grow + r1) * NFEAT + col) =
                make_float2(c[sl][nt][0], c[sl][nt][1]);
            *(float2*)(g_EW + (size_t)(grow + r2) * NFEAT + col) =
                make_float2(c[sl][nt][2], c[sl][nt][3]);
        }
    }
}

// ---------------- Kernel 2: tensor rnn (R10 struct + fp16-acc lo terms) ---
#define RS_SID   16
#define RS_U0    1024
#define RS_U1    (RS_U0 + 65536)
#define RS_HHI   (RS_U1 + 65536)
#define RS_HLO   (RS_HHI + 16 * 536 * 2)
#define RS_TOTAL (RS_HLO + 16 * 536 * 2)

__global__ __launch_bounds__(256, 1) void rnn_tensor_kernel(
    const int*  __restrict__ ids1,
    const int*  __restrict__ ids2,
    const float* __restrict__ bias,
    float* __restrict__ out)
{
    extern __shared__ __align__(1024) char rsm[];
    const unsigned smb = smem_u32(rsm);
    const int tid  = threadIdx.x;
    const int wid  = tid >> 5;
    const int lane = tid & 31;
    const int rb0  = blockIdx.x * 16;
    const int* myids = (rb0 < NBATCH) ? ids1 : ids2;
    const int rbase  = rb0 & (NBATCH - 1);

    int* s_id = (int*)(rsm + RS_SID);
    const unsigned mb0 = smb + 0, mb1 = smb + 8;
    const unsigned ubase0 = smb + RS_U0;
    const unsigned ubase1 = smb + RS_U1;
    const unsigned hhi = smb + RS_HHI;
    const unsigned hlo = smb + RS_HLO;
    __half* h_hi = (__half*)(rsm + RS_HHI);
    __half* h_lo = (__half*)(rsm + RS_HLO);

    for (int i = tid; i < 16 * 536; i += 256) { h_hi[i] = __half(0); h_lo[i] = __half(0); }
    if (tid == 0) { mbar_init(mb0, 1); mbar_init(mb1, 1); }
    __syncthreads();
    if (tid == 0) {
        bulk_load(ubase0, g_U16,          65536, mb0);
        bulk_load(ubase1, g_U16 + 32768,  65536, mb1);
    }

    const int n0w = wid * 64;

    float2 bias2[8];
#pragma unroll
    for (int nt = 0; nt < 8; nt++)
        bias2[nt] = *(const float2*)(bias + n0w + nt * 8 + (lane & 3) * 2);

    const int a_row  = lane & 15;
    const int a_koct = (lane >> 4) * 8;
    const int b_i    = lane & 7;
    const int b_seg  = lane >> 3;
    const int b_nadd = (b_seg & 2) ? 8 : 0;
    const int b_kadd = (b_seg & 1) ? 8 : 0;

    unsigned ph0 = 0, ph1 = 0;

    for (int t = 0; t < NSEQ; t++) {
        if (tid < 16) s_id[tid] = myids[(rbase + tid) * NSEQ + t];

        float c[8][4];         // main term (fp32 accum)
        unsigned cl[8][2];     // lo terms (fp16x2 accum)
#pragma unroll
        for (int nt = 0; nt < 8; nt++) {
#pragma unroll
            for (int q = 0; q < 4; q++) c[nt][q] = 0.f;
            cl[nt][0] = 0u; cl[nt][1] = 0u;
        }

#pragma unroll 1
        for (int c2 = 0; c2 < 8; c2++) {
#pragma unroll
            for (int hb = 0; hb < 2; hb++) {
                const int ck = c2 * 2 + hb;
                if (hb) { mbar_wait(mb1, ph1); ph1 ^= 1; }
                else    { mbar_wait(mb0, ph0); ph0 ^= 1; }
                const unsigned ub = hb ? ubase1 : ubase0;
#pragma unroll
                for (int kt = 0; kt < 2; kt++) {
                    const int kglob = ck * 32 + kt * 16 + a_koct;
                    unsigned ah[4], al[4];
                    const unsigned aoff = (unsigned)((a_row * 536 + kglob) * 2);
                    ldsm_x4(ah[0], ah[1], ah[2], ah[3], hhi + aoff);
                    ldsm_x4(al[0], al[1], al[2], al[3], hlo + aoff);
                    const int kk = kt * 16 + b_kadd;
#pragma unroll
                    for (int p = 0; p < 4; p++) {
                        const int n = n0w + p * 16 + b_nadd + b_i;
                        const unsigned boff = (unsigned)(u_hidx(n, kk) * 2);
                        unsigned bh0, bh1, bh2, bh3, bl0, bl1, bl2, bl3;
                        ldsm_x4(bh0, bh1, bh2, bh3, ub + boff);
                        ldsm_x4(bl0, bl1, bl2, bl3, ub + 32768 + boff);
                        // main: fp32 accum
                        mma16816(c[2 * p],     ah[0], ah[1], ah[2], ah[3], bh0, bh1);
                        mma16816(c[2 * p + 1], ah[0], ah[1], ah[2], ah[3], bh2, bh3);
                        // lo terms: fp16 accum
                        mma16816_h(cl[2 * p][0],     cl[2 * p][1],
                                   al[0], al[1], al[2], al[3], bh0, bh1);
                        mma16816_h(cl[2 * p + 1][0], cl[2 * p + 1][1],
                                   al[0], al[1], al[2], al[3], bh2, bh3);
                        mma16816_h(cl[2 * p][0],     cl[2 * p][1],
                                   ah[0], ah[1], ah[2], ah[3], bl0, bl1);
                        mma16816_h(cl[2 * p + 1][0], cl[2 * p + 1][1],
                                   ah[0], ah[1], ah[2], ah[3], bl2, bl3);
                    }
                }
                __syncthreads();
                if (tid == 0) {
                    const int nc = t * 16 + ck + 2;
                    if (nc < NSEQ * 16)
                        bulk_load(hb ? ubase1 : ubase0,
                                  g_U16 + (size_t)(nc & 15) * 32768, 65536,
                                  hb ? mb1 : mb0);
                }
            }
        }

        // fold fp16-acc lo terms into fp32 main accumulators
#pragma unroll
        for (int nt = 0; nt < 8; nt++) {
            __half2 lo01 = *(__half2*)&cl[nt][0];
            __half2 lo23 = *(__half2*)&cl[nt][1];
            c[nt][0] += __half2float(lo01.x);
            c[nt][1] += __half2float(lo01.y);
            c[nt][2] += __half2float(lo23.x);
            c[nt][3] += __half2float(lo23.y);
        }

        {
            const int r1 = lane >> 2;
            const int r2 = r1 + 8;
            const int gid1 = s_id[r1], gid2 = s_id[r2];
            const float* e1 = g_EW + (size_t)gid1 * NFEAT;
            const float* e2 = g_EW + (size_t)gid2 * NFEAT;
            float2 X1[8], X2[8];
#pragma unroll
            for (int nt = 0; nt < 8; nt++) {
                const int col = n0w + nt * 8 + (lane & 3) * 2;
                X1[nt] = *(const float2*)(e1 + col);
                X2[nt] = *(const float2*)(e2 + col);
            }
            const bool m1 = (gid1 != 0), m2 = (gid2 != 0);
#pragma unroll
            for (int nt = 0; nt < 8; nt++) {
                const int col = n0w + nt * 8 + (lane & 3) * 2;
                if (m1) {
                    float v0 = tanhf(c[nt][0] + X1[nt].x + bias2[nt].x);
                    float v1 = tanhf(c[nt][1] + X1[nt].y + bias2[nt].y);
                    __half p0 = __float2half_rn(v0);
                    __half p1 = __float2half_rn(v1);
                    *(__half2*)(h_hi + r1 * 536 + col) = __halves2half2(p0, p1);
                    *(__half2*)(h_lo + r1 * 536 + col) =
                        __halves2half2(__float2half_rn(v0 - __half2float(p0)),
                                       __float2half_rn(v1 - __half2float(p1)));
                }
                if (m2) {
                    float v2 = tanhf(c[nt][2] + X2[nt].x + bias2[nt].x);
                    float v3 = tanhf(c[nt][3] + X2[nt].y + bias2[nt].y);
                    __half p2 = __float2half_rn(v2);
                    __half p3 = __float2half_rn(v3);
                    *(__half2*)(h_hi + r2 * 536 + col) = __halves2half2(p2, p3);
                    *(__half2*)(h_lo + r2 * 536 + col) =
                        __halves2half2(__float2half_rn(v2 - __half2float(p2)),
                                       __float2half_rn(v3 - __half2float(p3)));
                }
            }
        }
        __syncthreads();
    }

    for (int i = tid; i < 16 * NFEAT; i += 256) {
        const int r = i >> 9, cc = i & 511;
        out[(size_t)(rb0 + r) * NFEAT + cc] =
            __half2float(h_hi[r * 536 + cc]) + __half2float(h_lo[r * 536 + cc]);
    }
}

// ---------------- Kernel 3: cosine similarity -----------------------------
__global__ __launch_bounds__(256) void sim_kernel(float* __restrict__ out)
{
    const int b    = blockIdx.x * 8 + (threadIdx.x >> 5);
    const int lane = threadIdx.x & 31;
    const float* s1 = out + (size_t)b * NFEAT;
    const float* s2 = out + (size_t)(NBATCH + b) * NFEAT;
    float dot = 0.f, q1 = 0.f, q2 = 0.f;
    for (int j = lane; j < NFEAT; j += 32) {
        float a = s1[j], c = s2[j];
        dot += a * c;
        q1  += a * a;
        q2  += c * c;
    }
#pragma unroll
    for (int o = 16; o > 0; o >>= 1) {
        dot += __shfl_xor_sync(0xffffffffu, dot, o);
        q1  += __shfl_xor_sync(0xffffffffu, q1,  o);
        q2  += __shfl_xor_sync(0xffffffffu, q2,  o);
    }
    if (lane == 0) {
        float n1 = sqrtf(fmaxf(q1, 1e-12f));
        float n2 = sqrtf(fmaxf(q2, 1e-12f));
        out[(size_t)NROWS * NFEAT + b] = dot / (n1 * n2);
    }
}

// ---------------- launch -------------------------------------------------
extern "C" void kernel_launch(void* const* d_in, const int* in_sizes, int n_in,
                              void* d_out, int out_size)
{
    (void)in_sizes; (void)n_in; (void)out_size;
    const int*   ids1 = (const int*)  d_in[0];
    const int*   ids2 = (const int*)  d_in[1];
    const float* emb  = (const float*)d_in[2];
    const float* W    = (const float*)d_in[3];
    const float* U    = (const float*)d_in[4];
    const float* bias = (const float*)d_in[5];
    float* out = (float*)d_out;

    cudaFuncSetAttribute(ew_mma_kernel,
                         cudaFuncAttributeMaxDynamicSharedMemorySize, EW_TOTAL);
    cudaFuncSetAttribute(rnn_tensor_kernel,
                         cudaFuncAttributeMaxDynamicSharedMemorySize, RS_TOTAL);

    prepU_kernel<<<(NFEAT * NFEAT + 255) / 256, 256>>>(U);
    prepA_kernel<<<NTILES, 256>>>(emb);
    prepW_kernel<<<(NEMB * NFEAT + 255) / 256, 256>>>(W);
    dim3 gew(4, NTILES);
    ew_mma_kernel<<<gew, 256, EW_TOTAL>>>();
    rnn_tensor_kernel<<<NROWS / 16, 256, RS_TOTAL>>>(ids1, ids2, bias, out);
    sim_kernel<<<NBATCH / 8, 256>>>(out);
}